// round 10
// baseline (speedup 1.0000x reference)
#include <cuda_runtime.h>
#include <cuda_fp16.h>
#include <cstdint>

// ---------------------------------------------------------------------------
// SimpleGCNNet:  Y = P^2 * X * W^T + b       (single fused kernel, one wave)
//   X: (2048, 2000) fp32, W: (128, 2000), b: (128,) -> Y: (32, 64, 128)
// Grid 129: blocks 0..127 = (batch mt 0..31) x (k-split ks 0..3, 512 k each,
//   zero-padded): Zp[ks][mt] = X[mt] @ W^T  (fp16 mma.sync, paired stages).
//   block 128: FAST build P -> P2t (batched vector loads), then g_built++.
// Last GEMM arriver per batch (mod-4 counter) sums 4 partials, applies
// P2 + bias, writes Y[mt]. 32 distinct tail blocks -> parallel tails.
// ---------------------------------------------------------------------------

#define NNODE 64
#define GM 2048
#define GK 2000
#define GH 128
#define KSPLIT 4
#define KSLICE 512
#define NPAIR 16
#define MT 64
#define EPSW 1e-6f

// GEMM smem: 2 buffers x 2 stages x 9216 B (stage: aH 64x48B @0, bH 128x48B @3072)
// tail apply: Zs 32768 + P2s 16384 = 49152 ; build: P 17408 + Pt 17408 + misc
#define STAGE_BYTES 9216
#define BUF_BYTES (2 * STAGE_BYTES)
#define SMEM_DYN_BYTES 49152

__device__ float g_P2t[NNODE * NNODE];    // [m][n] = P2[n][m]
__device__ float g_Zp[KSPLIT][GM * GH];
__device__ unsigned g_cnt[32];            // per-batch arrival counters (mod 4)
__device__ unsigned g_built;              // sticky: build block done at least once

// ---- helpers --------------------------------------------------------------
__device__ __forceinline__ uint32_t smem_u32(const void* p) {
    uint32_t a;
    asm("{ .reg .u64 t; cvta.to.shared.u64 t, %1; cvt.u32.u64 %0, t; }"
        : "=r"(a) : "l"(p));
    return a;
}
__device__ __forceinline__ unsigned long long pack2(float lo, float hi) {
    unsigned long long r;
    asm("mov.b64 %0, {%1, %2};" : "=l"(r) : "f"(lo), "f"(hi));
    return r;
}
__device__ __forceinline__ unsigned long long fma2(unsigned long long a,
                                                   unsigned long long b,
                                                   unsigned long long c) {
    unsigned long long d;
    asm("fma.rn.f32x2 %0, %1, %2, %3;" : "=l"(d) : "l"(a), "l"(b), "l"(c));
    return d;
}
__device__ __forceinline__ float2 unpack2(unsigned long long v) {
    float2 f;
    asm("mov.b64 {%0, %1}, %2;" : "=f"(f.x), "=f"(f.y) : "l"(v));
    return f;
}
__device__ __forceinline__ void ldsm4(uint32_t* r, uint32_t addr) {
    asm volatile("ldmatrix.sync.aligned.m8n8.x4.shared.b16 {%0,%1,%2,%3}, [%4];"
                 : "=r"(r[0]), "=r"(r[1]), "=r"(r[2]), "=r"(r[3]) : "r"(addr));
}
__device__ __forceinline__ void mma_f16(float* c, const uint32_t* a,
                                        uint32_t b0, uint32_t b1) {
    asm volatile(
        "mma.sync.aligned.m16n8k16.row.col.f32.f16.f16.f32 "
        "{%0,%1,%2,%3}, {%4,%5,%6,%7}, {%8,%9}, {%0,%1,%2,%3};"
        : "+f"(c[0]), "+f"(c[1]), "+f"(c[2]), "+f"(c[3])
        : "r"(a[0]), "r"(a[1]), "r"(a[2]), "r"(a[3]), "r"(b0), "r"(b1));
}
__device__ __forceinline__ void cvt_h2(float4 v, uint32_t& h0, uint32_t& h1) {
    asm("cvt.rn.f16x2.f32 %0, %1, %2;" : "=r"(h0) : "f"(v.y), "f"(v.x));
    asm("cvt.rn.f16x2.f32 %0, %1, %2;" : "=r"(h1) : "f"(v.w), "f"(v.z));
}
__device__ __forceinline__ void sts2(uint32_t addr, uint32_t a, uint32_t b) {
    asm volatile("st.shared.v2.b32 [%0], {%1, %2};" :: "r"(addr), "r"(a), "r"(b)
                 : "memory");
}

// ---------------------------------------------------------------------------
// FAST build P -> P2t. Batched vector loads (16 edges/thread), dual P/Pt for
// float4-dot P^2. Scratch in dynamic smem:
//   P @ 0 (17408), Pt @ 17408, deg @ 34816, dinv @ 35072, flag @ 35328
// ---------------------------------------------------------------------------
#define PSTR 68
__device__ void build_p2_body(char* dsm, const int* __restrict__ eiw,
                              const float* __restrict__ ew, int E) {
    float* P    = (float*)dsm;
    float* Pt   = (float*)(dsm + 17408);
    float* deg  = (float*)(dsm + 34816);
    float* dinv = (float*)(dsm + 35072);
    int*   flag = (int*)(dsm + 35328);
    const int tid = threadIdx.x;

    for (int i = tid; i < NNODE * PSTR; i += 256) { P[i] = 0.0f; Pt[i] = 0.0f; }
    if (tid < NNODE) deg[tid] = 1.0f;   // self-loop weight 1.0
    if (tid == 0) *flag = 0;
    __syncthreads();

    // dtype detect: int64 little-endian values in [0,64) -> odd words == 0
    if (tid < 64 && eiw[2 * tid + 1] != 0) atomicOr(flag, 1);
    __syncthreads();
    const bool is64 = (*flag == 0);
    const bool vec_ok = ((E & 3) == 0);

    // ---- pass 1: deg (dst, w) with batched vector loads ----
    for (int base = tid * 16; base < E; base += 256 * 16) {
        if (vec_ok && base + 16 <= E) {
            int dI[16]; float wv[16];
            if (is64) {
#pragma unroll
                for (int j = 0; j < 16; j += 2) {
                    int4 u = *(const int4*)&eiw[2 * E + 2 * (base + j)];
                    dI[j] = u.x & 63; dI[j + 1] = u.z & 63;
                }
            } else {
#pragma unroll
                for (int j = 0; j < 16; j += 4) {
                    int4 u = *(const int4*)&eiw[E + base + j];
                    dI[j] = u.x & 63; dI[j + 1] = u.y & 63;
                    dI[j + 2] = u.z & 63; dI[j + 3] = u.w & 63;
                }
            }
#pragma unroll
            for (int j = 0; j < 16; j += 4)
                *(float4*)&wv[j] = *(const float4*)&ew[base + j];
#pragma unroll
            for (int j = 0; j < 16; j++) {
                float w = wv[j] <= 0.0f ? EPSW : wv[j];
                atomicAdd(&deg[dI[j]], w);
            }
        } else {
            for (int j = 0; j < 16 && base + j < E; j++) {
                int e = base + j;
                int d = (is64 ? eiw[2 * E + 2 * e] : eiw[E + e]) & 63;
                float w = ew[e]; if (w <= 0.0f) w = EPSW;
                atomicAdd(&deg[d], w);
            }
        }
    }
    __syncthreads();
    if (tid < NNODE) {
        float d = deg[tid];
        dinv[tid] = (d > 0.0f) ? rsqrtf(d) : 0.0f;
    }
    __syncthreads();

    // ---- pass 2: P / Pt accumulation ----
    for (int base = tid * 16; base < E; base += 256 * 16) {
        if (vec_ok && base + 16 <= E) {
            int sI[16], dI[16]; float wv[16];
            if (is64) {
#pragma unroll
                for (int j = 0; j < 16; j += 2) {
                    int4 v = *(const int4*)&eiw[2 * (base + j)];
                    sI[j] = v.x & 63; sI[j + 1] = v.z & 63;
                    int4 u = *(const int4*)&eiw[2 * E + 2 * (base + j)];
                    dI[j] = u.x & 63; dI[j + 1] = u.z & 63;
                }
            } else {
#pragma unroll
                for (int j = 0; j < 16; j += 4) {
                    int4 v = *(const int4*)&eiw[base + j];
                    sI[j] = v.x & 63; sI[j + 1] = v.y & 63;
                    sI[j + 2] = v.z & 63; sI[j + 3] = v.w & 63;
                    int4 u = *(const int4*)&eiw[E + base + j];
                    dI[j] = u.x & 63; dI[j + 1] = u.y & 63;
                    dI[j + 2] = u.z & 63; dI[j + 3] = u.w & 63;
                }
            }
#pragma unroll
            for (int j = 0; j < 16; j += 4)
                *(float4*)&wv[j] = *(const float4*)&ew[base + j];
#pragma unroll
            for (int j = 0; j < 16; j++) {
                float w = wv[j] <= 0.0f ? EPSW : wv[j];
                float v = dinv[sI[j]] * w * dinv[dI[j]];
                atomicAdd(&P[dI[j] * PSTR + sI[j]], v);
                atomicAdd(&Pt[sI[j] * PSTR + dI[j]], v);
            }
        } else {
            for (int j = 0; j < 16 && base + j < E; j++) {
                int e = base + j;
                int s = (is64 ? eiw[2 * e] : eiw[e]) & 63;
                int d = (is64 ? eiw[2 * E + 2 * e] : eiw[E + e]) & 63;
                float w = ew[e]; if (w <= 0.0f) w = EPSW;
                float v = dinv[s] * w * dinv[d];
                atomicAdd(&P[d * PSTR + s], v);
                atomicAdd(&Pt[s * PSTR + d], v);
            }
        }
    }
    if (tid < NNODE) {
        float v = dinv[tid] * dinv[tid];
        atomicAdd(&P[tid * PSTR + tid], v);
        atomicAdd(&Pt[tid * PSTR + tid], v);
    }
    __syncthreads();

    // P2[r][c] = dot(P[r,:], Pt[c,:]) -> g_P2t[c*64 + r]
    const int r = tid >> 2;
    const int cb = tid & 3;
#pragma unroll
    for (int j = 0; j < 16; j++) {
        int c = cb + 4 * j;
        float acc = 0.0f;
#pragma unroll
        for (int m = 0; m < NNODE; m += 4) {
            float4 a = *(const float4*)&P[r * PSTR + m];
            float4 bt = *(const float4*)&Pt[c * PSTR + m];
            acc += a.x * bt.x + a.y * bt.y + a.z * bt.z + a.w * bt.w;
        }
        g_P2t[c * NNODE + r] = acc;
    }
    __syncthreads();
    if (tid == 0) {
        __threadfence();
        atomicAdd(&g_built, 1u);   // sticky ready flag (values identical per launch)
    }
}

// ---------------------------------------------------------------------------
// tail: Y[b] = P2 @ (sum_s Zp[s])[b] + bias     (reuses dynamic smem)
//   Zs @ 0 (32 KB), P2s @ 32768 (16 KB)
// ---------------------------------------------------------------------------
__device__ void apply_batch(char* dsm, int b, const float* __restrict__ bias,
                            float* __restrict__ y) {
    float* Zs  = (float*)dsm;
    float* P2s = (float*)(dsm + 32768);
    const int tid = threadIdx.x;

    __syncthreads();   // smem reuse guard
    for (int i = tid; i < NNODE * NNODE; i += 256) P2s[i] = g_P2t[i];
    for (int p = tid; p < 2048; p += 256) {
        int row = p >> 5;
        int c4 = (p & 31) * 4;
        const float* src = &g_Zp[0][((size_t)b * NNODE + row) * GH + c4];
        float4 s = *(const float4*)src;
#pragma unroll
        for (int si = 1; si < KSPLIT; si++) {
            float4 v = *(const float4*)(src + (size_t)si * GM * GH);
            s.x += v.x; s.y += v.y; s.z += v.z; s.w += v.w;
        }
        *(float4*)&Zs[row * GH + c4] = s;
    }
    __syncthreads();

    const int hp = tid & 63;          // h-pair 0..63
    const int n0 = (tid >> 6) * 16;   // 16 output rows per thread

    unsigned long long acc[16];
    float2 bv = *(const float2*)(bias + 2 * hp);
    unsigned long long bini = pack2(bv.x, bv.y);
#pragma unroll
    for (int i = 0; i < 16; i++) acc[i] = bini;

#pragma unroll 4
    for (int m = 0; m < NNODE; m++) {
        unsigned long long z = *(const unsigned long long*)&Zs[m * GH + 2 * hp];
#pragma unroll
        for (int j0 = 0; j0 < 16; j0 += 4) {
            float4 p4 = *(const float4*)&P2s[m * NNODE + n0 + j0];
            acc[j0 + 0] = fma2(pack2(p4.x, p4.x), z, acc[j0 + 0]);
            acc[j0 + 1] = fma2(pack2(p4.y, p4.y), z, acc[j0 + 1]);
            acc[j0 + 2] = fma2(pack2(p4.z, p4.z), z, acc[j0 + 2]);
            acc[j0 + 3] = fma2(pack2(p4.w, p4.w), z, acc[j0 + 3]);
        }
    }
#pragma unroll
    for (int i = 0; i < 16; i++) {
        float2 v = unpack2(acc[i]);
        *(float2*)&y[((size_t)b * NNODE + n0 + i) * GH + 2 * hp] = v;
    }
}

// ---------------------------------------------------------------------------
// Fused kernel
// ---------------------------------------------------------------------------
__global__ __launch_bounds__(256) void fused_kernel(
    const float* __restrict__ X, const float* __restrict__ W,
    const int* __restrict__ eiw, const float* __restrict__ ew, int E,
    const float* __restrict__ bias, float* __restrict__ y) {

    extern __shared__ __align__(1024) char smem[];
    __shared__ int s_last;
    const int tid = threadIdx.x;

    if (blockIdx.x == 128) { build_p2_body(smem, eiw, ew, E); return; }

    const uint32_t sb = smem_u32(smem);
    const int wid = tid >> 5;
    const int lane = tid & 31;

    const int mt = blockIdx.x & 31;       // batch 0..31
    const int ks = blockIdx.x >> 5;       // 0..3
    const int m_base = mt * MT;
    const int k0 = ks * KSLICE;
    const int nst = min(32, (GK - k0) >> 4);   // 32,32,32,29 real stages

    // loader roles (per 16-k stage)
    const int xrow = tid >> 2, xq = (tid & 3) * 4;
    const int brow = tid >> 1, bq = (tid & 1) * 8;
    const float* xp = X + (size_t)(m_base + xrow) * GK + k0 + xq;
    const float* wp = W + (size_t)brow * GK + k0 + bq;
    const uint32_t xoff = (uint32_t)(xrow * 48 + xq * 2);
    const uint32_t boff = (uint32_t)(brow * 48 + bq * 2);

    const int warp_m = wid >> 2, warp_n = wid & 3;

    float acc[32];
#pragma unroll
    for (int i = 0; i < 32; i++) acc[i] = 0.0f;

    const float4 fz = make_float4(0.f, 0.f, 0.f, 0.f);

    auto stsStage = [&](uint32_t stAddr, float4 xv, float4 w0, float4 w1) {
        uint32_t h0, h1;
        cvt_h2(xv, h0, h1); sts2(stAddr + xoff, h0, h1);
        cvt_h2(w0, h0, h1); sts2(stAddr + 3072 + boff, h0, h1);
        cvt_h2(w1, h0, h1); sts2(stAddr + 3072 + boff + 8, h0, h1);
    };

    // prologue: pair 0 (stages 0,1) -> buf0  (nst >= 29 > 5, unconditional)
    stsStage(sb, *(const float4*)xp, *(const float4*)wp, *(const float4*)(wp + 4));
    stsStage(sb + STAGE_BYTES, *(const float4*)(xp + 16),
             *(const float4*)(wp + 16), *(const float4*)(wp + 20));

    float4 xr[2][2], wr0[2][2], wr1[2][2];
#pragma unroll
    for (int pre = 1; pre <= 2; pre++) {
        const int s = pre & 1;
#pragma unroll
        for (int st = 0; st < 2; st++) {
            int g = 2 * pre + st;
            int off = g * 16;
            xr[s][st]  = *(const float4*)(xp + off);
            wr0[s][st] = *(const float4*)(wp + off);
            wr1[s][st] = *(const float4*)(wp + off + 4);
        }
    }
    __syncthreads();

    const uint32_t lrow = (uint32_t)(lane & 15);
    const uint32_t lkh = (uint32_t)(lane >> 4) * 16;
    const uint32_t raBase = (32u * warp_m + lrow) * 48 + lkh;
    const uint32_t rbBase = (32u * warp_n + lrow) * 48 + lkh + 3072;

    for (int t = 0; t < NPAIR; t++) {
        const uint32_t bufA = sb + (t & 1) * BUF_BYTES;

        uint32_t Ah[2][2][4], Bh[2][2][4];
#pragma unroll
        for (int st = 0; st < 2; st++) {
            const uint32_t stA = bufA + st * STAGE_BYTES;
#pragma unroll
            for (int f = 0; f < 2; f++) {
                ldsm4(Ah[st][f], stA + raBase + 768u * f);
                ldsm4(Bh[st][f], stA + rbBase + 768u * f);
            }
        }

        if (t + 1 < NPAIR) {
            const int s = (t + 1) & 1;
            const uint32_t so = sb + s * BUF_BYTES;
            stsStage(so, xr[s][0], wr0[s][0], wr1[s][0]);
            stsStage(so + STAGE_BYTES, xr[s][1], wr0[s][1], wr1[s][1]);
        }
        if (t + 3 < NPAIR) {
            const int s = (t + 3) & 1;
#pragma unroll
            for (int st = 0; st < 2; st++) {
                int g = 2 * (t + 3) + st;
                bool v = (g < nst);
                int off = g * 16;
                xr[s][st]  = v ? *(const float4*)(xp + off) : fz;
                wr0[s][st] = v ? *(const float4*)(wp + off) : fz;
                wr1[s][st] = v ? *(const float4*)(wp + off + 4) : fz;
            }
        }
        __syncthreads();

#pragma unroll
        for (int st = 0; st < 2; st++) {
#pragma unroll
            for (int f = 0; f < 2; f++) {
#pragma unroll
                for (int g = 0; g < 2; g++) {
                    float* c0 = acc + (f * 4 + 2 * g) * 4;
                    float* c1 = acc + (f * 4 + 2 * g + 1) * 4;
                    mma_f16(c0, Ah[st][f], Bh[st][g][0], Bh[st][g][2]);
                    mma_f16(c1, Ah[st][f], Bh[st][g][1], Bh[st][g][3]);
                }
            }
        }
    }

    // epilogue: write Z-partial
    float* zp = g_Zp[ks];
    const int cr = lane >> 2, cc = (lane & 3) * 2;
#pragma unroll
    for (int f = 0; f < 2; f++) {
#pragma unroll
        for (int nb = 0; nb < 4; nb++) {
            const float* c = acc + (f * 4 + nb) * 4;
            int row = m_base + 32 * warp_m + 16 * f + cr;
            int col = 32 * warp_n + 8 * nb + cc;
            *(float2*)&zp[(size_t)row * GH + col] = make_float2(c[0], c[1]);
            *(float2*)&zp[(size_t)(row + 8) * GH + col] = make_float2(c[2], c[3]);
        }
    }

    // arrival: last of 4 ks-blocks for this batch applies P2
    __syncthreads();
    if (tid == 0) {
        __threadfence();
        unsigned old = atomicAdd(&g_cnt[mt], 1u);
        s_last = (((old + 1) & 3) == 0) ? 1 : 0;
    }
    __syncthreads();
    if (s_last) {
        if (tid == 0) {
            while (atomicAdd(&g_built, 0u) == 0u) { }   // first launch only
            __threadfence();
        }
        apply_batch(smem, mt, bias, y);   // begins with __syncthreads()
    }
}

// ---------------------------------------------------------------------------
extern "C" void kernel_launch(void* const* d_in, const int* in_sizes, int n_in,
                              void* d_out, int out_size) {
    const float* x    = (const float*)d_in[0];
    const int*   eiw  = (const int*)d_in[1];
    const float* ew   = (const float*)d_in[2];
    const float* W    = (const float*)d_in[3];
    const float* bias = (const float*)d_in[4];
    float*       y    = (float*)d_out;

    const int E = in_sizes[1] / 2;

    static bool attr_set = false;
    if (!attr_set) {
        cudaFuncSetAttribute(fused_kernel,
                             cudaFuncAttributeMaxDynamicSharedMemorySize,
                             SMEM_DYN_BYTES);
        attr_set = true;
    }
    fused_kernel<<<129, 256, SMEM_DYN_BYTES>>>(x, W, eiw, ew, E, bias, y);
}

// round 11
// speedup vs baseline: 1.2626x; 1.2626x over previous
#include <cuda_runtime.h>
#include <cuda_fp16.h>
#include <cstdint>

// ---------------------------------------------------------------------------
// SimpleGCNNet:  Y = P^2 * X * W^T + b
//   X: (2048, 2000) fp32, W: (128, 2000), b: (128,) -> Y: (32, 64, 128)
// Kernel A (grid 129, one wave): blocks 0..127 = (batch mt) x (k-split ks,
//   512 k zero-padded): Zp[ks][mt] = X[mt] @ W^T  (fp16 mma.sync, paired
//   16-k stages). block 128: FAST build P -> P2t (batched vector loads).
// Kernel B (grid 128 x 512 thr): Y[b,:,hq:hq+32] = P2 @ (sum Zp)[b] + bias
// ---------------------------------------------------------------------------

#define NNODE 64
#define GM 2048
#define GK 2000
#define GH 128
#define KSPLIT 4
#define KSLICE 512
#define NPAIR 16
#define MT 64
#define EPSW 1e-6f

// GEMM smem: 2 buffers x 2 stages x 9216 B (stage: aH 64x48B @0, bH 128x48B @3072)
#define STAGE_BYTES 9216
#define BUF_BYTES (2 * STAGE_BYTES)
#define SMEM_DYN_BYTES (2 * BUF_BYTES)   // 36864 < 48KB default

__device__ float g_P2t[NNODE * NNODE];    // [m][n] = P2[n][m]
__device__ float g_Zp[KSPLIT][GM * GH];

// ---- helpers --------------------------------------------------------------
__device__ __forceinline__ uint32_t smem_u32(const void* p) {
    uint32_t a;
    asm("{ .reg .u64 t; cvta.to.shared.u64 t, %1; cvt.u32.u64 %0, t; }"
        : "=r"(a) : "l"(p));
    return a;
}
__device__ __forceinline__ unsigned long long pack2(float lo, float hi) {
    unsigned long long r;
    asm("mov.b64 %0, {%1, %2};" : "=l"(r) : "f"(lo), "f"(hi));
    return r;
}
__device__ __forceinline__ unsigned long long fma2(unsigned long long a,
                                                   unsigned long long b,
                                                   unsigned long long c) {
    unsigned long long d;
    asm("fma.rn.f32x2 %0, %1, %2, %3;" : "=l"(d) : "l"(a), "l"(b), "l"(c));
    return d;
}
__device__ __forceinline__ float2 unpack2(unsigned long long v) {
    float2 f;
    asm("mov.b64 {%0, %1}, %2;" : "=f"(f.x), "=f"(f.y) : "l"(v));
    return f;
}
__device__ __forceinline__ void ldsm4(uint32_t* r, uint32_t addr) {
    asm volatile("ldmatrix.sync.aligned.m8n8.x4.shared.b16 {%0,%1,%2,%3}, [%4];"
                 : "=r"(r[0]), "=r"(r[1]), "=r"(r[2]), "=r"(r[3]) : "r"(addr));
}
__device__ __forceinline__ void mma_f16(float* c, const uint32_t* a,
                                        uint32_t b0, uint32_t b1) {
    asm volatile(
        "mma.sync.aligned.m16n8k16.row.col.f32.f16.f16.f32 "
        "{%0,%1,%2,%3}, {%4,%5,%6,%7}, {%8,%9}, {%0,%1,%2,%3};"
        : "+f"(c[0]), "+f"(c[1]), "+f"(c[2]), "+f"(c[3])
        : "r"(a[0]), "r"(a[1]), "r"(a[2]), "r"(a[3]), "r"(b0), "r"(b1));
}
__device__ __forceinline__ void cvt_h2(float4 v, uint32_t& h0, uint32_t& h1) {
    asm("cvt.rn.f16x2.f32 %0, %1, %2;" : "=r"(h0) : "f"(v.y), "f"(v.x));
    asm("cvt.rn.f16x2.f32 %0, %1, %2;" : "=r"(h1) : "f"(v.w), "f"(v.z));
}
__device__ __forceinline__ void sts2(uint32_t addr, uint32_t a, uint32_t b) {
    asm volatile("st.shared.v2.b32 [%0], {%1, %2};" :: "r"(addr), "r"(a), "r"(b)
                 : "memory");
}

// ---------------------------------------------------------------------------
// FAST build P -> P2t. Batched vector loads (16 edges/thread), dual P/Pt for
// float4-dot P^2. Scratch in dynamic smem:
//   P @ 0 (17408), Pt @ 17408, deg @ 34816, dinv @ 35072, flag @ 35328
// ---------------------------------------------------------------------------
#define PSTR 68
__device__ void build_p2_body(char* dsm, const int* __restrict__ eiw,
                              const float* __restrict__ ew, int E) {
    float* P    = (float*)dsm;
    float* Pt   = (float*)(dsm + 17408);
    float* deg  = (float*)(dsm + 34816);
    float* dinv = (float*)(dsm + 35072);
    int*   flag = (int*)(dsm + 35328);
    const int tid = threadIdx.x;

    for (int i = tid; i < NNODE * PSTR; i += 256) { P[i] = 0.0f; Pt[i] = 0.0f; }
    if (tid < NNODE) deg[tid] = 1.0f;   // self-loop weight 1.0
    if (tid == 0) *flag = 0;
    __syncthreads();

    // dtype detect: int64 little-endian values in [0,64) -> odd words == 0
    if (tid < 64 && eiw[2 * tid + 1] != 0) atomicOr(flag, 1);
    __syncthreads();
    const bool is64 = (*flag == 0);
    const bool vec_ok = ((E & 3) == 0);

    // ---- pass 1: deg (dst, w) ----
    for (int base = tid * 16; base < E; base += 256 * 16) {
        if (vec_ok && base + 16 <= E) {
            int dI[16]; float wv[16];
            if (is64) {
#pragma unroll
                for (int j = 0; j < 16; j += 2) {
                    int4 u = *(const int4*)&eiw[2 * E + 2 * (base + j)];
                    dI[j] = u.x & 63; dI[j + 1] = u.z & 63;
                }
            } else {
#pragma unroll
                for (int j = 0; j < 16; j += 4) {
                    int4 u = *(const int4*)&eiw[E + base + j];
                    dI[j] = u.x & 63; dI[j + 1] = u.y & 63;
                    dI[j + 2] = u.z & 63; dI[j + 3] = u.w & 63;
                }
            }
#pragma unroll
            for (int j = 0; j < 16; j += 4)
                *(float4*)&wv[j] = *(const float4*)&ew[base + j];
#pragma unroll
            for (int j = 0; j < 16; j++) {
                float w = wv[j] <= 0.0f ? EPSW : wv[j];
                atomicAdd(&deg[dI[j]], w);
            }
        } else {
            for (int j = 0; j < 16 && base + j < E; j++) {
                int e = base + j;
                int d = (is64 ? eiw[2 * E + 2 * e] : eiw[E + e]) & 63;
                float w = ew[e]; if (w <= 0.0f) w = EPSW;
                atomicAdd(&deg[d], w);
            }
        }
    }
    __syncthreads();
    if (tid < NNODE) {
        float d = deg[tid];
        dinv[tid] = (d > 0.0f) ? rsqrtf(d) : 0.0f;
    }
    __syncthreads();

    // ---- pass 2: P / Pt accumulation ----
    for (int base = tid * 16; base < E; base += 256 * 16) {
        if (vec_ok && base + 16 <= E) {
            int sI[16], dI[16]; float wv[16];
            if (is64) {
#pragma unroll
                for (int j = 0; j < 16; j += 2) {
                    int4 v = *(const int4*)&eiw[2 * (base + j)];
                    sI[j] = v.x & 63; sI[j + 1] = v.z & 63;
                    int4 u = *(const int4*)&eiw[2 * E + 2 * (base + j)];
                    dI[j] = u.x & 63; dI[j + 1] = u.z & 63;
                }
            } else {
#pragma unroll
                for (int j = 0; j < 16; j += 4) {
                    int4 v = *(const int4*)&eiw[base + j];
                    sI[j] = v.x & 63; sI[j + 1] = v.y & 63;
                    sI[j + 2] = v.z & 63; sI[j + 3] = v.w & 63;
                    int4 u = *(const int4*)&eiw[E + base + j];
                    dI[j] = u.x & 63; dI[j + 1] = u.y & 63;
                    dI[j + 2] = u.z & 63; dI[j + 3] = u.w & 63;
                }
            }
#pragma unroll
            for (int j = 0; j < 16; j += 4)
                *(float4*)&wv[j] = *(const float4*)&ew[base + j];
#pragma unroll
            for (int j = 0; j < 16; j++) {
                float w = wv[j] <= 0.0f ? EPSW : wv[j];
                float v = dinv[sI[j]] * w * dinv[dI[j]];
                atomicAdd(&P[dI[j] * PSTR + sI[j]], v);
                atomicAdd(&Pt[sI[j] * PSTR + dI[j]], v);
            }
        } else {
            for (int j = 0; j < 16 && base + j < E; j++) {
                int e = base + j;
                int s = (is64 ? eiw[2 * e] : eiw[e]) & 63;
                int d = (is64 ? eiw[2 * E + 2 * e] : eiw[E + e]) & 63;
                float w = ew[e]; if (w <= 0.0f) w = EPSW;
                float v = dinv[s] * w * dinv[d];
                atomicAdd(&P[d * PSTR + s], v);
                atomicAdd(&Pt[s * PSTR + d], v);
            }
        }
    }
    if (tid < NNODE) {
        float v = dinv[tid] * dinv[tid];
        atomicAdd(&P[tid * PSTR + tid], v);
        atomicAdd(&Pt[tid * PSTR + tid], v);
    }
    __syncthreads();

    // P2[r][c] = dot(P[r,:], Pt[c,:]) -> g_P2t[c*64 + r]
    const int r = tid >> 2;
    const int cb = tid & 3;
#pragma unroll
    for (int j = 0; j < 16; j++) {
        int c = cb + 4 * j;
        float acc = 0.0f;
#pragma unroll
        for (int m = 0; m < NNODE; m += 4) {
            float4 a = *(const float4*)&P[r * PSTR + m];
            float4 bt = *(const float4*)&Pt[c * PSTR + m];
            acc += a.x * bt.x + a.y * bt.y + a.z * bt.z + a.w * bt.w;
        }
        g_P2t[c * NNODE + r] = acc;
    }
}

// ---------------------------------------------------------------------------
// Kernel A: fp16 mma GEMM partials (paired k-stages) + fast P2 build
// ---------------------------------------------------------------------------
__global__ __launch_bounds__(256) void gemm_build_kernel(
    const float* __restrict__ X, const float* __restrict__ W,
    const int* __restrict__ eiw, const float* __restrict__ ew, int E) {

    extern __shared__ __align__(1024) char smem[];

    if (blockIdx.x == 128) { build_p2_body(smem, eiw, ew, E); return; }

    const uint32_t sb = smem_u32(smem);
    const int tid = threadIdx.x;
    const int wid = tid >> 5;
    const int lane = tid & 31;

    const int mt = blockIdx.x & 31;       // batch 0..31
    const int ks = blockIdx.x >> 5;       // 0..3
    const int m_base = mt * MT;
    const int k0 = ks * KSLICE;
    const int nst = min(32, (GK - k0) >> 4);   // 32,32,32,29 real stages

    // loader roles (per 16-k stage)
    const int xrow = tid >> 2, xq = (tid & 3) * 4;
    const int brow = tid >> 1, bq = (tid & 1) * 8;
    const float* xp = X + (size_t)(m_base + xrow) * GK + k0 + xq;
    const float* wp = W + (size_t)brow * GK + k0 + bq;
    const uint32_t xoff = (uint32_t)(xrow * 48 + xq * 2);
    const uint32_t boff = (uint32_t)(brow * 48 + bq * 2);

    const int warp_m = wid >> 2, warp_n = wid & 3;

    float acc[32];
#pragma unroll
    for (int i = 0; i < 32; i++) acc[i] = 0.0f;

    const float4 fz = make_float4(0.f, 0.f, 0.f, 0.f);

    auto stsStage = [&](uint32_t stAddr, float4 xv, float4 w0, float4 w1) {
        uint32_t h0, h1;
        cvt_h2(xv, h0, h1); sts2(stAddr + xoff, h0, h1);
        cvt_h2(w0, h0, h1); sts2(stAddr + 3072 + boff, h0, h1);
        cvt_h2(w1, h0, h1); sts2(stAddr + 3072 + boff + 8, h0, h1);
    };

    // prologue: pair 0 (stages 0,1) -> buf0 ; stages 2..5 in regs (nst>=29)
    stsStage(sb, *(const float4*)xp, *(const float4*)wp, *(const float4*)(wp + 4));
    stsStage(sb + STAGE_BYTES, *(const float4*)(xp + 16),
             *(const float4*)(wp + 16), *(const float4*)(wp + 20));

    float4 xr[2][2], wr0[2][2], wr1[2][2];
#pragma unroll
    for (int pre = 1; pre <= 2; pre++) {
        const int s = pre & 1;
#pragma unroll
        for (int st = 0; st < 2; st++) {
            int g = 2 * pre + st;
            int off = g * 16;
            xr[s][st]  = *(const float4*)(xp + off);
            wr0[s][st] = *(const float4*)(wp + off);
            wr1[s][st] = *(const float4*)(wp + off + 4);
        }
    }
    __syncthreads();

    const uint32_t lrow = (uint32_t)(lane & 15);
    const uint32_t lkh = (uint32_t)(lane >> 4) * 16;
    const uint32_t raBase = (32u * warp_m + lrow) * 48 + lkh;
    const uint32_t rbBase = (32u * warp_n + lrow) * 48 + lkh + 3072;

    for (int t = 0; t < NPAIR; t++) {
        const uint32_t bufA = sb + (t & 1) * BUF_BYTES;

        uint32_t Ah[2][2][4], Bh[2][2][4];
#pragma unroll
        for (int st = 0; st < 2; st++) {
            const uint32_t stA = bufA + st * STAGE_BYTES;
#pragma unroll
            for (int f = 0; f < 2; f++) {
                ldsm4(Ah[st][f], stA + raBase + 768u * f);
                ldsm4(Bh[st][f], stA + rbBase + 768u * f);
            }
        }

        if (t + 1 < NPAIR) {
            const int s = (t + 1) & 1;
            const uint32_t so = sb + s * BUF_BYTES;
            stsStage(so, xr[s][0], wr0[s][0], wr1[s][0]);
            stsStage(so + STAGE_BYTES, xr[s][1], wr0[s][1], wr1[s][1]);
        }
        if (t + 3 < NPAIR) {
            const int s = (t + 3) & 1;
#pragma unroll
            for (int st = 0; st < 2; st++) {
                int g = 2 * (t + 3) + st;
                bool v = (g < nst);
                int off = g * 16;
                xr[s][st]  = v ? *(const float4*)(xp + off) : fz;
                wr0[s][st] = v ? *(const float4*)(wp + off) : fz;
                wr1[s][st] = v ? *(const float4*)(wp + off + 4) : fz;
            }
        }
        __syncthreads();

#pragma unroll
        for (int st = 0; st < 2; st++) {
#pragma unroll
            for (int f = 0; f < 2; f++) {
#pragma unroll
                for (int g = 0; g < 2; g++) {
                    float* c0 = acc + (f * 4 + 2 * g) * 4;
                    float* c1 = acc + (f * 4 + 2 * g + 1) * 4;
                    mma_f16(c0, Ah[st][f], Bh[st][g][0], Bh[st][g][2]);
                    mma_f16(c1, Ah[st][f], Bh[st][g][1], Bh[st][g][3]);
                }
            }
        }
    }

    // epilogue: write Z-partial
    float* zp = g_Zp[ks];
    const int cr = lane >> 2, cc = (lane & 3) * 2;
#pragma unroll
    for (int f = 0; f < 2; f++) {
#pragma unroll
        for (int nb = 0; nb < 4; nb++) {
            const float* c = acc + (f * 4 + nb) * 4;
            int row = m_base + 32 * warp_m + 16 * f + cr;
            int col = 32 * warp_n + 8 * nb + cc;
            *(float2*)&zp[(size_t)row * GH + col] = make_float2(c[0], c[1]);
            *(float2*)&zp[(size_t)(row + 8) * GH + col] = make_float2(c[2], c[3]);
        }
    }
}

// ---------------------------------------------------------------------------
// Kernel B: Y[b,:,hq:hq+32] = P2 @ (sum_s Zp[s])[b,:,hq:hq+32] + bias
// grid 128 = 32 batches x 4 h-quarters ; 512 threads
// ---------------------------------------------------------------------------
__global__ __launch_bounds__(512) void apply_p2_kernel(
    const float* __restrict__ bias, float* __restrict__ y) {
    __shared__ __align__(16) float P2t[NNODE * NNODE];  // [m][n] 16 KB
    __shared__ __align__(16) float Zs[NNODE * 32];      // [m][hc] 8 KB
    const int b = blockIdx.x >> 2;
    const int hq = (blockIdx.x & 3) * 32;
    const int tid = threadIdx.x;

    for (int i = tid; i < NNODE * NNODE; i += 512)
        P2t[i] = g_P2t[i];

    {   // sum 4 Z-partials: 64 rows x 32 cols = 512 float4, one per thread
        int m = tid >> 3;
        int c4 = (tid & 7) * 4;
        const float* src = &g_Zp[0][((size_t)b * NNODE + m) * GH + hq + c4];
        float4 s = *(const float4*)src;
#pragma unroll
        for (int si = 1; si < KSPLIT; si++) {
            float4 v = *(const float4*)(src + (size_t)si * GM * GH);
            s.x += v.x; s.y += v.y; s.z += v.z; s.w += v.w;
        }
        *(float4*)&Zs[m * 32 + c4] = s;
    }
    __syncthreads();

    const int hp = tid & 15;          // h-pair within quarter
    const int n0 = (tid >> 4) * 2;    // 2 output rows per thread

    unsigned long long acc0, acc1;
    float2 bv = *(const float2*)(bias + hq + 2 * hp);
    acc0 = acc1 = pack2(bv.x, bv.y);

#pragma unroll 8
    for (int m = 0; m < NNODE; m++) {
        unsigned long long z = *(const unsigned long long*)&Zs[m * 32 + 2 * hp];
        float2 p = *(const float2*)&P2t[m * NNODE + n0];
        acc0 = fma2(pack2(p.x, p.x), z, acc0);
        acc1 = fma2(pack2(p.y, p.y), z, acc1);
    }

    float* yb = y + ((size_t)b * NNODE + n0) * GH + hq + 2 * hp;
    float2 v0 = unpack2(acc0), v1 = unpack2(acc1);
    *(float2*)yb = v0;
    *(float2*)(yb + GH) = v1;
}

// ---------------------------------------------------------------------------
extern "C" void kernel_launch(void* const* d_in, const int* in_sizes, int n_in,
                              void* d_out, int out_size) {
    const float* x    = (const float*)d_in[0];
    const int*   eiw  = (const int*)d_in[1];
    const float* ew   = (const float*)d_in[2];
    const float* W    = (const float*)d_in[3];
    const float* bias = (const float*)d_in[4];
    float*       y    = (float*)d_out;

    const int E = in_sizes[1] / 2;

    gemm_build_kernel<<<129, 256, SMEM_DYN_BYTES>>>(x, W, eiw, ew, E);
    apply_p2_kernel<<<128, 512>>>(bias, y);
}